// round 6
// baseline (speedup 1.0000x reference)
#include <cuda_runtime.h>
#include <cstdint>

// Problem constants
#define BATCH   8192
#define MSIZE   128
#define NBLK    32                 // ICOUNT = MCOUNT = OCOUNT
#define BN      (BATCH * MSIZE)    // 1048576 elems per c-slab

// Scratch: Y[c][b][n] (tf32-rounded), Z[c][b][m]  (128 MB each)
__device__ float g_Y[(size_t)NBLK * BN];
__device__ float g_Z[(size_t)NBLK * BN];

// ---------------- helpers ----------------
typedef unsigned long long ull;

__device__ __forceinline__ ull pk2(float lo, float hi) {
    ull r;
    asm("mov.b64 %0, {%1, %2};" : "=l"(r) : "f"(lo), "f"(hi));
    return r;
}
__device__ __forceinline__ void up2(ull v, float& lo, float& hi) {
    asm("mov.b64 {%0, %1}, %2;" : "=f"(lo), "=f"(hi) : "l"(v));
}
// packed fp32x2 FMA (Blackwell FFMA2): d = a*b + c componentwise
__device__ __forceinline__ ull ff2(ull a, ull b, ull c) {
    ull d;
    asm("fma.rn.f32x2 %0, %1, %2, %3;" : "=l"(d) : "l"(a), "l"(b), "l"(c));
    return d;
}
// round fp32 -> tf32 (fp32 bit pattern, low mantissa cleared)
__device__ __forceinline__ float tf32r(float v) {
    unsigned u;
    asm("cvt.rna.tf32.f32 %0, %1;" : "=r"(u) : "f"(v));
    return __uint_as_float(u);
}
__device__ __forceinline__ void mma_tf32(float& d0, float& d1, float& d2, float& d3,
                                         unsigned a0, unsigned a1, unsigned a2, unsigned a3,
                                         unsigned b0, unsigned b1) {
    asm volatile(
        "mma.sync.aligned.m16n8k8.row.col.f32.tf32.tf32.f32 "
        "{%0,%1,%2,%3}, {%4,%5,%6,%7}, {%8,%9}, {%0,%1,%2,%3};"
        : "+f"(d0), "+f"(d1), "+f"(d2), "+f"(d3)
        : "r"(a0), "r"(a1), "r"(a2), "r"(a3), "r"(b0), "r"(b1));
}

// ---------------- Stage 1 ----------------
// Y[c][b][n] = sum_i x[b, i*128+n] * W_in[c,i] + b_in[c]
// 256 threads: n = tid&127, half = tid>>7 owns 8 c-pairs. 2 batch rows per CTA.
__global__ void __launch_bounds__(256, 3) k_stage1(const float* __restrict__ x,
                                                   const float* __restrict__ Win,
                                                   const float* __restrict__ bin) {
    __shared__ ull wp[32][16];  // [i][cp] = (W_in[2cp][i], W_in[2cp+1][i])
    __shared__ ull bp[16];
    const int tid = threadIdx.x;
    for (int idx = tid; idx < 512; idx += 256) {
        const int cp = idx & 15, i = idx >> 4;
        wp[i][cp] = pk2(Win[(2 * cp) * 32 + i], Win[(2 * cp + 1) * 32 + i]);
    }
    if (tid < 16) bp[tid] = pk2(bin[2 * tid], bin[2 * tid + 1]);
    __syncthreads();

    const int n   = tid & 127;
    const int cpb = (tid >> 7) * 8;     // half 0 -> cp 0..7, half 1 -> cp 8..15
    const size_t bA = (size_t)blockIdx.x * 2, bB = bA + 1;
    const float* xa = x + bA * 4096 + n;
    const float* xb = x + bB * 4096 + n;

    ull accA[8], accB[8];
#pragma unroll
    for (int j = 0; j < 8; j++) { accA[j] = bp[cpb + j]; accB[j] = bp[cpb + j]; }

#pragma unroll 4
    for (int i = 0; i < 32; i++) {
        const float va = xa[(size_t)i * 128];
        const float vb = xb[(size_t)i * 128];
        const ull ua = pk2(va, va);
        const ull ub = pk2(vb, vb);
#pragma unroll
        for (int j = 0; j < 8; j++) {
            const ull w = wp[i][cpb + j];
            accA[j] = ff2(ua, w, accA[j]);
            accB[j] = ff2(ub, w, accB[j]);
        }
    }
#pragma unroll
    for (int j = 0; j < 8; j++) {
        const int cp = cpb + j;
        float l, hh;
        up2(accA[j], l, hh);
        g_Y[(size_t)(2 * cp) * BN + bA * 128 + n]     = tf32r(l);
        g_Y[(size_t)(2 * cp + 1) * BN + bA * 128 + n] = tf32r(hh);
        up2(accB[j], l, hh);
        g_Y[(size_t)(2 * cp) * BN + bB * 128 + n]     = tf32r(l);
        g_Y[(size_t)(2 * cp + 1) * BN + bB * 128 + n] = tf32r(hh);
    }
}

// ---------------- Stage 2 ----------------
// per c: Z[c][b][m] = sum_n Y[c][b][n] * W_mods[c][m][n] + b_mods[c][m]
// grid (64 batch tiles, 32 c), 256 threads (8 warps; warp = 64x32 subtile of 128x128).
// tf32 mma m16n8k8; W chunks register-prefetched + double-buffered in smem.
#define AS_LD 132
#define BS_LD 36
#define BS_SZ (128 * BS_LD)
#define SMEM2_FLOATS (128 * AS_LD + 2 * BS_SZ + 128)

__global__ void __launch_bounds__(256, 2) k_stage2(const float* __restrict__ Wm,
                                                   const float* __restrict__ bmods) {
    extern __shared__ float sm[];
    float* As  = sm;                          // [128][AS_LD]
    float* Bs  = sm + 128 * AS_LD;            // 2 x [128][BS_LD]
    float* bmS = sm + 128 * AS_LD + 2 * BS_SZ;

    const int tid = threadIdx.x;
    const int c   = blockIdx.y;
    const int bt  = blockIdx.x;

    const float* Wc = Wm + (size_t)c * 16384;

    // prefetch W chunk 0 into registers (4 float4 per thread)
    float4 pre[4];
#pragma unroll
    for (int j = 0; j < 4; j++) {
        const int i = tid + j * 256;               // 0..1023
        const int mm = i >> 3, cc = (i & 7) << 2;
        pre[j] = *(const float4*)(Wc + mm * 128 + cc);
    }

    // A tile: contiguous 64KB of g_Y (already tf32-rounded)
    const float4* As4 = (const float4*)(g_Y + (size_t)c * BN + (size_t)bt * 16384);
#pragma unroll
    for (int i = tid; i < 4096; i += 256) {
        const int r = i >> 5, cc = (i & 31) << 2;
        *(float4*)&As[r * AS_LD + cc] = As4[i];
    }
    if (tid < 128) bmS[tid] = bmods[c * 128 + tid];

    // commit chunk 0 into buffer 0
#pragma unroll
    for (int j = 0; j < 4; j++) {
        const int i = tid + j * 256;
        const int mm = i >> 3, cc = (i & 7) << 2;
        float4 v = pre[j];
        v.x = tf32r(v.x); v.y = tf32r(v.y); v.z = tf32r(v.z); v.w = tf32r(v.w);
        *(float4*)&Bs[mm * BS_LD + cc] = v;
    }
    __syncthreads();   // As + Bs0 ready

    const int lane = tid & 31, warp = tid >> 5;
    const int g = lane >> 2, tg = lane & 3;
    const int wr = (warp & 1) * 64;        // row offset (2 warps over 128 rows)
    const int wc = (warp >> 1) * 32;       // col offset (4 warps over 128 cols)

    float acc[4][4][4];
#pragma unroll
    for (int rt = 0; rt < 4; rt++)
#pragma unroll
        for (int ct = 0; ct < 4; ct++)
#pragma unroll
            for (int j = 0; j < 4; j++) acc[rt][ct][j] = 0.0f;

#pragma unroll 1
    for (int kc = 0; kc < 4; kc++) {
        // prefetch next chunk (overlaps with MMA below)
        if (kc < 3) {
#pragma unroll
            for (int j = 0; j < 4; j++) {
                const int i = tid + j * 256;
                const int mm = i >> 3, cc = (i & 7) << 2;
                pre[j] = *(const float4*)(Wc + mm * 128 + (kc + 1) * 32 + cc);
            }
        }
        const float* Bcur = Bs + (kc & 1) * BS_SZ;

#pragma unroll
        for (int ks = 0; ks < 4; ks++) {
            const int kA = kc * 32 + ks * 8;
            const int kB = ks * 8;
            unsigned a0[4], a1[4], a2[4], a3[4], b0[4], b1[4];
#pragma unroll
            for (int rt = 0; rt < 4; rt++) {
                const int r0 = wr + rt * 16 + g;
                a0[rt] = __float_as_uint(As[r0 * AS_LD + kA + tg]);
                a1[rt] = __float_as_uint(As[(r0 + 8) * AS_LD + kA + tg]);
                a2[rt] = __float_as_uint(As[r0 * AS_LD + kA + tg + 4]);
                a3[rt] = __float_as_uint(As[(r0 + 8) * AS_LD + kA + tg + 4]);
            }
#pragma unroll
            for (int ct = 0; ct < 4; ct++) {
                const int mcol = wc + ct * 8 + g;
                b0[ct] = __float_as_uint(Bcur[mcol * BS_LD + kB + tg]);
                b1[ct] = __float_as_uint(Bcur[mcol * BS_LD + kB + tg + 4]);
            }
#pragma unroll
            for (int rt = 0; rt < 4; rt++)
#pragma unroll
                for (int ct = 0; ct < 4; ct++)
                    mma_tf32(acc[rt][ct][0], acc[rt][ct][1], acc[rt][ct][2], acc[rt][ct][3],
                             a0[rt], a1[rt], a2[rt], a3[rt], b0[ct], b1[ct]);
        }

        if (kc < 3) {
            // store chunk kc+1 into the other buffer; safe: its readers (iter kc-1)
            // all passed the previous barrier.
            float* Bnxt = Bs + ((kc + 1) & 1) * BS_SZ;
#pragma unroll
            for (int j = 0; j < 4; j++) {
                const int i = tid + j * 256;
                const int mm = i >> 3, cc = (i & 7) << 2;
                float4 v = pre[j];
                v.x = tf32r(v.x); v.y = tf32r(v.y); v.z = tf32r(v.z); v.w = tf32r(v.w);
                *(float4*)&Bnxt[mm * BS_LD + cc] = v;
            }
            __syncthreads();
        }
    }

    // epilogue: add bias, write Z[c][b][m]
#pragma unroll
    for (int rt = 0; rt < 4; rt++) {
        const int r0 = wr + rt * 16 + g;
        const size_t gb0 = (size_t)c * BN + ((size_t)bt * 128 + r0) * 128;
#pragma unroll
        for (int ct = 0; ct < 4; ct++) {
            const int m0 = wc + ct * 8 + tg * 2;
            const float bv0 = bmS[m0], bv1 = bmS[m0 + 1];
            float2 v0 = make_float2(acc[rt][ct][0] + bv0, acc[rt][ct][1] + bv1);
            float2 v1 = make_float2(acc[rt][ct][2] + bv0, acc[rt][ct][3] + bv1);
            *(float2*)&g_Z[gb0 + m0]        = v0;   // row r0
            *(float2*)&g_Z[gb0 + 1024 + m0] = v1;   // row r0+8
        }
    }
}

// ---------------- Stage 3 ----------------
// out[b, m*32+o] = sum_c Z[c][b][m] * W_out[o,c] + b_out[o]
// 256 threads: m = tid&127, half = tid>>7 owns 8 o-pairs. 2 batch rows per CTA.
#define ST_LD 36
__global__ void __launch_bounds__(256, 3) k_stage3(const float* __restrict__ Wout,
                                                   const float* __restrict__ bout,
                                                   float* __restrict__ out) {
    __shared__ ull wp[32][16];  // [c][op] = (W_out[2op][c], W_out[2op+1][c])
    __shared__ ull bp[16];
    __shared__ float sT[2][128 * ST_LD];
    const int tid = threadIdx.x;
    for (int idx = tid; idx < 512; idx += 256) {
        const int op = idx & 15, cc = idx >> 4;
        wp[cc][op] = pk2(Wout[(2 * op) * 32 + cc], Wout[(2 * op + 1) * 32 + cc]);
    }
    if (tid < 16) bp[tid] = pk2(bout[2 * tid], bout[2 * tid + 1]);
    __syncthreads();

    const int m   = tid & 127;
    const int opb = (tid >> 7) * 8;
    const size_t bA = (size_t)blockIdx.x * 2, bB = bA + 1;

    ull accA[8], accB[8];
#pragma unroll
    for (int j = 0; j < 8; j++) { accA[j] = bp[opb + j]; accB[j] = bp[opb + j]; }

#pragma unroll 4
    for (int cc = 0; cc < 32; cc++) {
        const float za = g_Z[(size_t)cc * BN + bA * 128 + m];
        const float zb = g_Z[(size_t)cc * BN + bB * 128 + m];
        const ull ua = pk2(za, za);
        const ull ub = pk2(zb, zb);
#pragma unroll
        for (int j = 0; j < 8; j++) {
            const ull w = wp[cc][opb + j];
            accA[j] = ff2(ua, w, accA[j]);
            accB[j] = ff2(ub, w, accB[j]);
        }
    }

    // transpose through smem for coalesced float4 stores
#pragma unroll
    for (int j = 0; j < 8; j++) {
        const int op = opb + j;
        float l, hh;
        up2(accA[j], l, hh);
        sT[0][m * ST_LD + 2 * op] = l; sT[0][m * ST_LD + 2 * op + 1] = hh;
        up2(accB[j], l, hh);
        sT[1][m * ST_LD + 2 * op] = l; sT[1][m * ST_LD + 2 * op + 1] = hh;
    }
    __syncthreads();
#pragma unroll
    for (int k = 0; k < 4; k++) {
        const int j = (k * 256 + tid) * 4;
        const int mr = j >> 5, o = j & 31;
        *(float4*)&out[bA * 4096 + j] = *(const float4*)&sT[0][mr * ST_LD + o];
        *(float4*)&out[bB * 4096 + j] = *(const float4*)&sT[1][mr * ST_LD + o];
    }
}

// ---------------- launch ----------------
extern "C" void kernel_launch(void* const* d_in, const int* in_sizes, int n_in,
                              void* d_out, int out_size) {
    (void)in_sizes; (void)n_in; (void)out_size;
    const float* x      = (const float*)d_in[0];
    const float* W_in   = (const float*)d_in[1];
    const float* b_in   = (const float*)d_in[2];
    const float* W_mods = (const float*)d_in[3];
    const float* b_mods = (const float*)d_in[4];
    const float* W_out  = (const float*)d_in[5];
    const float* b_out  = (const float*)d_in[6];
    float* out = (float*)d_out;

    const int smem2 = SMEM2_FLOATS * (int)sizeof(float);  // 104960 bytes
    cudaFuncSetAttribute(k_stage2, cudaFuncAttributeMaxDynamicSharedMemorySize, smem2);

    k_stage1<<<BATCH / 2, 256>>>(x, W_in, b_in);
    k_stage2<<<dim3(BATCH / 128, NBLK), 256, smem2>>>(W_mods, b_mods);
    k_stage3<<<BATCH / 2, 256>>>(W_out, b_out, out);
}

// round 7
// speedup vs baseline: 1.2241x; 1.2241x over previous
#include <cuda_runtime.h>
#include <cstdint>

// Problem constants
#define BATCH   8192
#define MSIZE   128
#define NBLK    32                 // ICOUNT = MCOUNT = OCOUNT
#define BN      (BATCH * MSIZE)    // 1048576 elems per c-slab

// Scratch: Y[c][b][n] (tf32-rounded), Z[c][b][m]  (128 MB each)
__device__ float g_Y[(size_t)NBLK * BN];
__device__ float g_Z[(size_t)NBLK * BN];

// ---------------- helpers ----------------
typedef unsigned long long ull;

__device__ __forceinline__ ull pk2(float lo, float hi) {
    ull r;
    asm("mov.b64 %0, {%1, %2};" : "=l"(r) : "f"(lo), "f"(hi));
    return r;
}
__device__ __forceinline__ void up2(ull v, float& lo, float& hi) {
    asm("mov.b64 {%0, %1}, %2;" : "=f"(lo), "=f"(hi) : "l"(v));
}
// packed fp32x2 FMA (Blackwell FFMA2): d = a*b + c componentwise
__device__ __forceinline__ ull ff2(ull a, ull b, ull c) {
    ull d;
    asm("fma.rn.f32x2 %0, %1, %2, %3;" : "=l"(d) : "l"(a), "l"(b), "l"(c));
    return d;
}
// round fp32 -> tf32 (fp32 bit pattern, low mantissa cleared)
__device__ __forceinline__ float tf32r(float v) {
    unsigned u;
    asm("cvt.rna.tf32.f32 %0, %1;" : "=r"(u) : "f"(v));
    return __uint_as_float(u);
}
__device__ __forceinline__ void mma_tf32(float& d0, float& d1, float& d2, float& d3,
                                         unsigned a0, unsigned a1, unsigned a2, unsigned a3,
                                         unsigned b0, unsigned b1) {
    asm volatile(
        "mma.sync.aligned.m16n8k8.row.col.f32.tf32.tf32.f32 "
        "{%0,%1,%2,%3}, {%4,%5,%6,%7}, {%8,%9}, {%0,%1,%2,%3};"
        : "+f"(d0), "+f"(d1), "+f"(d2), "+f"(d3)
        : "r"(a0), "r"(a1), "r"(a2), "r"(a3), "r"(b0), "r"(b1));
}

// ---------------- Stage 1 ----------------
// Y[c][b][n] = sum_i x[b, i*128+n] * W_in[c,i] + b_in[c]
// 128 threads (one n each), 2 batch rows per CTA.
// Two sequential half-passes over c (8 pairs each) -> half the accumulator regs,
// 5 CTAs/SM. Second pass re-reads x from L1. Weight loads are LDS.128.
__global__ void __launch_bounds__(128, 5) k_stage1(const float* __restrict__ x,
                                                   const float* __restrict__ Win,
                                                   const float* __restrict__ bin) {
    __shared__ ull wp[32][16];  // [i][cp] = (W_in[2cp][i], W_in[2cp+1][i]); row=128B aligned
    __shared__ ull bp[16];
    const int tid = threadIdx.x;
    for (int idx = tid; idx < 512; idx += 128) {
        const int cp = idx & 15, i = idx >> 4;
        wp[i][cp] = pk2(Win[(2 * cp) * 32 + i], Win[(2 * cp + 1) * 32 + i]);
    }
    if (tid < 16) bp[tid] = pk2(bin[2 * tid], bin[2 * tid + 1]);
    __syncthreads();

    const int n = tid;
    const size_t bA = (size_t)blockIdx.x * 2, bB = bA + 1;
    const float* xa = x + bA * 4096 + n;
    const float* xb = x + bB * 4096 + n;

#pragma unroll 1
    for (int h = 0; h < 2; h++) {
        const int cpb = h * 8;
        ull accA[8], accB[8];
#pragma unroll
        for (int j = 0; j < 8; j++) { accA[j] = bp[cpb + j]; accB[j] = bp[cpb + j]; }

#pragma unroll 8
        for (int i = 0; i < 32; i++) {
            const float va = xa[(size_t)i * 128];
            const float vb = xb[(size_t)i * 128];
            const ull ua = pk2(va, va);
            const ull ub = pk2(vb, vb);
#pragma unroll
            for (int jj = 0; jj < 4; jj++) {
                const ulonglong2 w2 = *(const ulonglong2*)&wp[i][cpb + 2 * jj];
                accA[2 * jj]     = ff2(ua, w2.x, accA[2 * jj]);
                accB[2 * jj]     = ff2(ub, w2.x, accB[2 * jj]);
                accA[2 * jj + 1] = ff2(ua, w2.y, accA[2 * jj + 1]);
                accB[2 * jj + 1] = ff2(ub, w2.y, accB[2 * jj + 1]);
            }
        }
#pragma unroll
        for (int j = 0; j < 8; j++) {
            const int cp = cpb + j;
            float l, hh;
            up2(accA[j], l, hh);
            g_Y[(size_t)(2 * cp) * BN + bA * 128 + n]     = tf32r(l);
            g_Y[(size_t)(2 * cp + 1) * BN + bA * 128 + n] = tf32r(hh);
            up2(accB[j], l, hh);
            g_Y[(size_t)(2 * cp) * BN + bB * 128 + n]     = tf32r(l);
            g_Y[(size_t)(2 * cp + 1) * BN + bB * 128 + n] = tf32r(hh);
        }
    }
}

// ---------------- Stage 2 (R5 config — best measured) ----------------
// per c: Z[c][b][m] = sum_n Y[c][b][n] * W_mods[c][m][n] + b_mods[c][m]
// grid (64 batch tiles, 32 c), 256 threads (8 warps; warp = 64x32 subtile of 128x128).
// tf32 mma m16n8k8; W chunks register-prefetched to overlap global latency with MMA.
#define AS_LD 132
#define BS_LD 36
#define SMEM2_FLOATS (128 * AS_LD + 128 * BS_LD + 128)

__global__ void __launch_bounds__(256, 2) k_stage2(const float* __restrict__ Wm,
                                                   const float* __restrict__ bmods) {
    extern __shared__ float sm[];
    float* As  = sm;                             // [128][AS_LD]
    float* Bs  = sm + 128 * AS_LD;               // [128][BS_LD]  (m-major, k minor)
    float* bmS = sm + 128 * AS_LD + 128 * BS_LD; // [128]

    const int tid = threadIdx.x;
    const int c   = blockIdx.y;
    const int bt  = blockIdx.x;

    const float* Wc = Wm + (size_t)c * 16384;

    // prefetch W chunk 0 into registers (4 float4 per thread)
    float4 pre[4];
#pragma unroll
    for (int j = 0; j < 4; j++) {
        const int i = tid + j * 256;               // 0..1023
        const int mm = i >> 3, cc = (i & 7) << 2;
        pre[j] = *(const float4*)(Wc + mm * 128 + cc);
    }

    // A tile: contiguous 64KB of g_Y (already tf32-rounded)
    const float4* As4 = (const float4*)(g_Y + (size_t)c * BN + (size_t)bt * 16384);
#pragma unroll
    for (int i = tid; i < 4096; i += 256) {
        const int r = i >> 5, cc = (i & 31) << 2;
        *(float4*)&As[r * AS_LD + cc] = As4[i];
    }
    if (tid < 128) bmS[tid] = bmods[c * 128 + tid];

    const int lane = tid & 31, warp = tid >> 5;
    const int g = lane >> 2, tg = lane & 3;
    const int wr = (warp & 1) * 64;        // row offset (2 warps over 128 rows)
    const int wc = (warp >> 1) * 32;       // col offset (4 warps over 128 cols)

    float acc[4][4][4];
#pragma unroll
    for (int rt = 0; rt < 4; rt++)
#pragma unroll
        for (int ct = 0; ct < 4; ct++)
#pragma unroll
            for (int j = 0; j < 4; j++) acc[rt][ct][j] = 0.0f;

#pragma unroll 1
    for (int kc = 0; kc < 4; kc++) {
        __syncthreads();  // A ready (kc=0) / Bs consumers done (kc>0)
        // commit prefetched W chunk to smem (tf32-rounded)
#pragma unroll
        for (int j = 0; j < 4; j++) {
            const int i = tid + j * 256;
            const int mm = i >> 3, cc = (i & 7) << 2;
            float4 v = pre[j];
            v.x = tf32r(v.x); v.y = tf32r(v.y); v.z = tf32r(v.z); v.w = tf32r(v.w);
            *(float4*)&Bs[mm * BS_LD + cc] = v;
        }
        __syncthreads();
        // prefetch next chunk (overlaps with MMA below)
        if (kc < 3) {
#pragma unroll
            for (int j = 0; j < 4; j++) {
                const int i = tid + j * 256;
                const int mm = i >> 3, cc = (i & 7) << 2;
                pre[j] = *(const float4*)(Wc + mm * 128 + (kc + 1) * 32 + cc);
            }
        }

#pragma unroll
        for (int ks = 0; ks < 4; ks++) {
            const int kA = kc * 32 + ks * 8;
            const int kB = ks * 8;
            unsigned a0[4], a1[4], a2[4], a3[4], b0[4], b1[4];
#pragma unroll
            for (int rt = 0; rt < 4; rt++) {
                const int r0 = wr + rt * 16 + g;
                a0[rt] = __float_as_uint(As[r0 * AS_LD + kA + tg]);
                a1[rt] = __float_as_uint(As[(r0 + 8) * AS_LD + kA + tg]);
                a2[rt] = __float_as_uint(As[r0 * AS_LD + kA + tg + 4]);
                a3[rt] = __float_as_uint(As[(r0 + 8) * AS_LD + kA + tg + 4]);
            }
#pragma unroll
            for (int ct = 0; ct < 4; ct++) {
                const int mcol = wc + ct * 8 + g;
                b0[ct] = __float_as_uint(Bs[mcol * BS_LD + kB + tg]);
                b1[ct] = __float_as_uint(Bs[mcol * BS_LD + kB + tg + 4]);
            }
#pragma unroll
            for (int rt = 0; rt < 4; rt++)
#pragma unroll
                for (int ct = 0; ct < 4; ct++)
                    mma_tf32(acc[rt][ct][0], acc[rt][ct][1], acc[rt][ct][2], acc[rt][ct][3],
                             a0[rt], a1[rt], a2[rt], a3[rt], b0[ct], b1[ct]);
        }
    }

    // epilogue: add bias, write Z[c][b][m]
#pragma unroll
    for (int rt = 0; rt < 4; rt++) {
        const int r0 = wr + rt * 16 + g;
        const size_t gb0 = (size_t)c * BN + ((size_t)bt * 128 + r0) * 128;
#pragma unroll
        for (int ct = 0; ct < 4; ct++) {
            const int m0 = wc + ct * 8 + tg * 2;
            const float bv0 = bmS[m0], bv1 = bmS[m0 + 1];
            float2 v0 = make_float2(acc[rt][ct][0] + bv0, acc[rt][ct][1] + bv1);
            float2 v1 = make_float2(acc[rt][ct][2] + bv0, acc[rt][ct][3] + bv1);
            *(float2*)&g_Z[gb0 + m0]        = v0;   // row r0
            *(float2*)&g_Z[gb0 + 1024 + m0] = v1;   // row r0+8
        }
    }
}

// ---------------- Stage 3 ----------------
// out[b, m*32+o] = sum_c Z[c][b][m] * W_out[o,c] + b_out[o]
// Same split-pass structure as stage 1; transpose via smem for float4 stores.
#define ST_LD 36
__global__ void __launch_bounds__(128, 5) k_stage3(const float* __restrict__ Wout,
                                                   const float* __restrict__ bout,
                                                   float* __restrict__ out) {
    __shared__ ull wp[32][16];  // [c][op] = (W_out[2op][c], W_out[2op+1][c])
    __shared__ ull bp[16];
    __shared__ float sT[2][128 * ST_LD];
    const int tid = threadIdx.x;
    for (int idx = tid; idx < 512; idx += 128) {
        const int op = idx & 15, cc = idx >> 4;
        wp[cc][op] = pk2(Wout[(2 * op) * 32 + cc], Wout[(2 * op + 1) * 32 + cc]);
    }
    if (tid < 16) bp[tid] = pk2(bout[2 * tid], bout[2 * tid + 1]);
    __syncthreads();

    const int m = tid;
    const size_t bA = (size_t)blockIdx.x * 2, bB = bA + 1;
    const float* za0 = g_Z + bA * 128 + m;
    const float* zb0 = g_Z + bB * 128 + m;

#pragma unroll 1
    for (int h = 0; h < 2; h++) {
        const int opb = h * 8;
        ull accA[8], accB[8];
#pragma unroll
        for (int j = 0; j < 8; j++) { accA[j] = bp[opb + j]; accB[j] = bp[opb + j]; }

#pragma unroll 8
        for (int cc = 0; cc < 32; cc++) {
            const float za = za0[(size_t)cc * BN];
            const float zb = zb0[(size_t)cc * BN];
            const ull ua = pk2(za, za);
            const ull ub = pk2(zb, zb);
#pragma unroll
            for (int jj = 0; jj < 4; jj++) {
                const ulonglong2 w2 = *(const ulonglong2*)&wp[cc][opb + 2 * jj];
                accA[2 * jj]     = ff2(ua, w2.x, accA[2 * jj]);
                accB[2 * jj]     = ff2(ub, w2.x, accB[2 * jj]);
                accA[2 * jj + 1] = ff2(ua, w2.y, accA[2 * jj + 1]);
                accB[2 * jj + 1] = ff2(ub, w2.y, accB[2 * jj + 1]);
            }
        }
#pragma unroll
        for (int j = 0; j < 8; j++) {
            const int op = opb + j;
            float l, hh;
            up2(accA[j], l, hh);
            sT[0][m * ST_LD + 2 * op] = l; sT[0][m * ST_LD + 2 * op + 1] = hh;
            up2(accB[j], l, hh);
            sT[1][m * ST_LD + 2 * op] = l; sT[1][m * ST_LD + 2 * op + 1] = hh;
        }
    }
    __syncthreads();
#pragma unroll
    for (int k = 0; k < 8; k++) {
        const int j = (k * 128 + tid) * 4;
        const int mr = j >> 5, o = j & 31;
        *(float4*)&out[bA * 4096 + j] = *(const float4*)&sT[0][mr * ST_LD + o];
        *(float4*)&out[bB * 4096 + j] = *(const float4*)&sT[1][mr * ST_LD + o];
    }
}

// ---------------- launch ----------------
extern "C" void kernel_launch(void* const* d_in, const int* in_sizes, int n_in,
                              void* d_out, int out_size) {
    (void)in_sizes; (void)n_in; (void)out_size;
    const float* x      = (const float*)d_in[0];
    const float* W_in   = (const float*)d_in[1];
    const float* b_in   = (const float*)d_in[2];
    const float* W_mods = (const float*)d_in[3];
    const float* b_mods = (const float*)d_in[4];
    const float* W_out  = (const float*)d_in[5];
    const float* b_out  = (const float*)d_in[6];
    float* out = (float*)d_out;

    const int smem2 = SMEM2_FLOATS * (int)sizeof(float);  // 86528 bytes
    cudaFuncSetAttribute(k_stage2, cudaFuncAttributeMaxDynamicSharedMemorySize, smem2);

    k_stage1<<<BATCH / 2, 128>>>(x, W_in, b_in);
    k_stage2<<<dim3(BATCH / 128, NBLK), 256, smem2>>>(W_mods, b_mods);
    k_stage3<<<BATCH / 2, 128>>>(W_out, b_out, out);
}